// round 4
// baseline (speedup 1.0000x reference)
#include <cuda_runtime.h>
#include <cstdint>

#define H 128
#define W 128
#define NS 8
#define TY 16
#define SROWS (TY + 8)   // 24
#define SCOLS 138        // 128 + 8 halo + pad; even => float2 alignment holds

__device__ __forceinline__ float2 ffma2(float2 a, float2 b, float2 c) {
    float2 d;
    asm("fma.rn.f32x2 %0, %1, %2, %3;"
        : "=l"(reinterpret_cast<uint64_t&>(d))
        : "l"(reinterpret_cast<uint64_t&>(a)),
          "l"(reinterpret_cast<uint64_t&>(b)),
          "l"(reinterpret_cast<uint64_t&>(c)));
    return d;
}

// 4 output rows x 2 cols for one (s, x-subtile).
// pa = &s_a[rowbase][col0], pb = &s_b[rowbase][col0].
// PAR = col0 & 1 (== sx & 1). Tap j is an aligned LDS.64:
//   ((j ^ PAR) & 1) == 0  ->  s_a at col0+j        (even index)
//   else                   ->  s_b at col0+j-1      (even index)
template<int PAR>
__device__ __forceinline__ void conv4(const float* __restrict__ pa,
                                      const float* __restrict__ pb,
                                      const float2* __restrict__ fp,
                                      float* __restrict__ op)
{
    float2 acc[4];
    #pragma unroll
    for (int y = 0; y < 4; ++y) acc[y] = make_float2(0.f, 0.f);

    #pragma unroll
    for (int k = 0; k < 8; ++k) {
        const float* ra = pa + k * SCOLS;
        const float* rb = pb + k * SCOLS;
        float2 p[5];
        #pragma unroll
        for (int j = 0; j < 5; ++j) {
            if (((j ^ PAR) & 1) == 0)
                p[j] = *(const float2*)(ra + j);        // aligned
            else
                p[j] = *(const float2*)(rb + (j - 1));  // aligned
        }
        #pragma unroll
        for (int y = 0; y < 4; ++y) {
            const int i = k - y;              // compile-time after unroll
            if (i >= 0 && i < 5) {
                acc[y] = ffma2(fp[i * 5 + 0], p[0], acc[y]);
                acc[y] = ffma2(fp[i * 5 + 1], p[1], acc[y]);
                acc[y] = ffma2(fp[i * 5 + 2], p[2], acc[y]);
                acc[y] = ffma2(fp[i * 5 + 3], p[3], acc[y]);
                acc[y] = ffma2(fp[i * 5 + 4], p[4], acc[y]);
            }
        }
    }
    #pragma unroll
    for (int y = 0; y < 4; ++y)
        *(float2*)(op + y * W) = acc[y];      // STG.64, aligned
}

__global__ void __launch_bounds__(128, 5)
shifted_conv_kernel(const float* __restrict__ tens,
                    const float* __restrict__ filters,
                    const int* __restrict__ shifts,
                    float* __restrict__ out)
{
    __shared__ __align__(16) float s_a[SROWS][SCOLS];   // x[c]
    __shared__ __align__(16) float s_b[SROWS][SCOLS];   // x[c+1]
    __shared__ float2 s_fp[NS * 25];
    __shared__ int    s_sh[NS * 2];

    const int n    = blockIdx.x;        // 0..255 (B*C)
    const int y0   = blockIdx.y * TY;   // 0..112 step 16
    const int tid  = threadIdx.x;
    const int lane = tid & 31;
    const int wrp  = tid >> 5;

    for (int i = tid; i < NS * 25; i += 128) {
        float f = filters[i];
        s_fp[i] = make_float2(f, f);
    }
    if (tid < NS * 2) s_sh[tid] = shifts[tid];

    const float* inp = tens + (size_t)n * (H * W);
    for (int idx = tid; idx < SROWS * SCOLS; idx += 128) {
        int r  = idx / SCOLS;
        int c  = idx - r * SCOLS;
        int gy = y0 - 4 + r;
        int gx = c - 4;
        float v = 0.0f;
        if (gy >= 0 && gy < H && gx >= 0 && gx < W)
            v = inp[gy * W + gx];
        s_a[r][c] = v;
        if (c > 0) s_b[r][c - 1] = v;
    }
    // s_b last column: value of x at SCOLS (out of range) - never read, but
    // initialize to keep determinism.
    for (int r = tid; r < SROWS; r += 128) s_b[r][SCOLS - 1] = 0.0f;
    __syncthreads();

    const int ybase = wrp * 4;          // 4 output rows per warp
    float* outw = out + (size_t)n * (NS * H * W) + (size_t)(y0 + ybase) * W;

    #pragma unroll 1
    for (int s = 0; s < NS; ++s) {
        const int sy = s_sh[2 * s + 0];
        const int sx = s_sh[2 * s + 1];

        float2 fp[25];
        #pragma unroll
        for (int t = 0; t < 25; ++t) fp[t] = s_fp[s * 25 + t];

        const int rowbase = ybase + 4 - sy;     // [0, 16]
        const int col0    = 2 * lane + 4 - sx;  // parity == parity of sx
        float* ops = outw + (size_t)s * (H * W) + 2 * lane;

        const float* pa = &s_a[rowbase][col0];
        const float* pb = &s_b[rowbase][col0];

        if (!(sx & 1)) {
            conv4<0>(pa,      pb,      fp, ops);
            conv4<0>(pa + 64, pb + 64, fp, ops + 64);
        } else {
            conv4<1>(pa,      pb,      fp, ops);
            conv4<1>(pa + 64, pb + 64, fp, ops + 64);
        }
    }
}

extern "C" void kernel_launch(void* const* d_in, const int* in_sizes, int n_in,
                              void* d_out, int out_size)
{
    const float* tens    = (const float*)d_in[0];
    const float* filters = (const float*)d_in[1];
    const int*   shifts  = (const int*)d_in[2];
    float*       out     = (float*)d_out;

    dim3 grid(256, H / TY);   // 2048 blocks
    shifted_conv_kernel<<<grid, 128>>>(tens, filters, shifts, out);
}

// round 5
// speedup vs baseline: 1.0056x; 1.0056x over previous
#include <cuda_runtime.h>
#include <cstdint>

#define H 128
#define W 128
#define NS 8
#define TY 16
#define SROWS (TY + 8)   // 24
#define SCOLS 138        // even => float2 row alignment preserved

__device__ __forceinline__ float2 ffma2(float2 a, float2 b, float2 c) {
    float2 d;
    asm("fma.rn.f32x2 %0, %1, %2, %3;"
        : "=l"(reinterpret_cast<uint64_t&>(d))
        : "l"(reinterpret_cast<uint64_t&>(a)),
          "l"(reinterpret_cast<uint64_t&>(b)),
          "l"(reinterpret_cast<uint64_t&>(c)));
    return d;
}

__global__ void __launch_bounds__(128, 5)
shifted_conv_kernel(const float* __restrict__ tens,
                    const float* __restrict__ filters,
                    const int* __restrict__ shifts,
                    float* __restrict__ out)
{
    __shared__ __align__(16) float s_a[SROWS][SCOLS];   // x[c]
    __shared__ __align__(16) float s_b[SROWS][SCOLS];   // x[c+1]
    __shared__ float2 s_fp[NS * 25];
    __shared__ int    s_sh[NS * 2];

    const int n    = blockIdx.x;        // 0..255 (B*C)
    const int y0   = blockIdx.y * TY;   // 0..112 step 16
    const int tid  = threadIdx.x;
    const int lane = tid & 31;
    const int wrp  = tid >> 5;

    for (int i = tid; i < NS * 25; i += 128) {
        float f = filters[i];
        s_fp[i] = make_float2(f, f);
    }
    if (tid < NS * 2) s_sh[tid] = shifts[tid];

    const float* inp = tens + (size_t)n * (H * W);
    for (int idx = tid; idx < SROWS * SCOLS; idx += 128) {
        int r  = idx / SCOLS;
        int c  = idx - r * SCOLS;
        int gy = y0 - 4 + r;
        int gx = c - 4;
        float v = 0.0f;
        if (gy >= 0 && gy < H && gx >= 0 && gx < W)
            v = inp[gy * W + gx];
        s_a[r][c] = v;
        if (c > 0) s_b[r][c - 1] = v;
    }
    for (int r = tid; r < SROWS; r += 128) s_b[r][SCOLS - 1] = 0.0f;
    __syncthreads();

    const int ybase = wrp * 4;          // 4 output rows per warp
    const int xo    = 4 * lane;         // 4 output cols per lane (full width)
    float* outw = out + (size_t)n * (NS * H * W)
                      + (size_t)(y0 + ybase) * W + xo;

    #pragma unroll 1
    for (int s = 0; s < NS; ++s) {
        const int sy = s_sh[2 * s + 0];
        const int sx = s_sh[2 * s + 1];

        float2 fp[25];
        #pragma unroll
        for (int t = 0; t < 25; ++t) fp[t] = s_fp[s * 25 + t];

        const int rowbase = ybase + 4 - sy;     // [0, 16]
        const int col0    = xo + 4 - sx;        // window start; parity = sx&1

        // Window base: w[t] = x_padded[col0 + t]. Always 8B-aligned:
        //   sx even -> col0 even, read s_a[col0]
        //   sx odd  -> col0 odd,  read s_b[col0-1]  (s_b[i] = x[i+1])
        const float* base = (sx & 1) ? &s_b[rowbase][col0 - 1]
                                     : &s_a[rowbase][col0];

        // acc[y][0] = outputs (xo, xo+1), acc[y][1] = (xo+2, xo+3)
        float2 acc[4][2];
        #pragma unroll
        for (int y = 0; y < 4; ++y) {
            acc[y][0] = make_float2(0.f, 0.f);
            acc[y][1] = make_float2(0.f, 0.f);
        }

        #pragma unroll
        for (int k = 0; k < 8; ++k) {
            const float2* r2 = (const float2*)(base + k * SCOLS);
            float2 q0 = r2[0], q1 = r2[1], q2 = r2[2], q3 = r2[3];
            // tap-pairs by window start: even starts are q's, odd are packs
            float2 p0 = q0;
            float2 p1 = make_float2(q0.y, q1.x);
            float2 p2 = q1;
            float2 p3 = make_float2(q1.y, q2.x);
            float2 p4 = q2;
            float2 p5 = make_float2(q2.y, q3.x);
            float2 p6 = q3;
            const float2 pp[7] = {p0, p1, p2, p3, p4, p5, p6};

            #pragma unroll
            for (int y = 0; y < 4; ++y) {
                const int i = k - y;          // compile-time after unroll
                if (i >= 0 && i < 5) {
                    #pragma unroll
                    for (int j = 0; j < 5; ++j) {
                        acc[y][0] = ffma2(fp[i * 5 + j], pp[j],     acc[y][0]);
                        acc[y][1] = ffma2(fp[i * 5 + j], pp[j + 2], acc[y][1]);
                    }
                }
            }
        }

        float* ops = outw + (size_t)s * (H * W);
        #pragma unroll
        for (int y = 0; y < 4; ++y) {
            float4 v = make_float4(acc[y][0].x, acc[y][0].y,
                                   acc[y][1].x, acc[y][1].y);
            *(float4*)(ops + y * W) = v;      // STG.128, 16B aligned
        }
    }
}

extern "C" void kernel_launch(void* const* d_in, const int* in_sizes, int n_in,
                              void* d_out, int out_size)
{
    const float* tens    = (const float*)d_in[0];
    const float* filters = (const float*)d_in[1];
    const int*   shifts  = (const int*)d_in[2];
    float*       out     = (float*)d_out;

    dim3 grid(256, H / TY);   // 2048 blocks
    shifted_conv_kernel<<<grid, 128>>>(tens, filters, shifts, out);
}

// round 6
// speedup vs baseline: 1.1175x; 1.1113x over previous
#include <cuda_runtime.h>
#include <cstdint>

#define H 128
#define W 128
#define NS 8
#define TY 16
#define SROWS (TY + 8)   // 24
#define SCOLS 136        // 128 + 8 halo; even => float2 alignment holds

typedef unsigned long long u64;

// In-place packed FMA: acc = a*b + acc. "+l" keeps acc in one register pair.
__device__ __forceinline__ void fma2(u64& acc, u64 a, u64 b) {
    asm("fma.rn.f32x2 %0, %1, %2, %0;" : "+l"(acc) : "l"(a), "l"(b));
}
// Pack two floats into a b64 pair (coalesced to 0 MOVs when already paired).
__device__ __forceinline__ u64 pk(float lo, float hi) {
    u64 r;
    asm("mov.b64 %0, {%1, %2};" : "=l"(r) : "f"(lo), "f"(hi));
    return r;
}

__global__ void __launch_bounds__(128)
shifted_conv_kernel(const float* __restrict__ tens,
                    const float* __restrict__ filters,
                    const int* __restrict__ shifts,
                    float* __restrict__ out)
{
    __shared__ __align__(16) float s_a[SROWS][SCOLS];   // x[c]
    __shared__ __align__(16) float s_b[SROWS][SCOLS];   // x[c+1]
    __shared__ float s_f[NS * 25];
    __shared__ int   s_sh[NS * 2];

    const int n    = blockIdx.x;        // 0..255 (B*C)
    const int y0   = blockIdx.y * TY;   // 0..112 step 16
    const int tid  = threadIdx.x;
    const int lane = tid & 31;
    const int wrp  = tid >> 5;

    for (int i = tid; i < NS * 25; i += 128) s_f[i] = filters[i];
    if (tid < NS * 2) s_sh[tid] = shifts[tid];

    const float* inp = tens + (size_t)n * (H * W);
    for (int idx = tid; idx < SROWS * SCOLS; idx += 128) {
        int r  = idx / SCOLS;
        int c  = idx - r * SCOLS;
        int gy = y0 - 4 + r;
        int gx = c - 4;
        float v = 0.0f;
        if (gy >= 0 && gy < H && gx >= 0 && gx < W)
            v = inp[gy * W + gx];
        s_a[r][c] = v;
        if (c > 0) s_b[r][c - 1] = v;
    }
    for (int r = tid; r < SROWS; r += 128) s_b[r][SCOLS - 1] = 0.0f;
    __syncthreads();

    const int ybase = wrp * 4;          // 4 output rows per warp
    const int xo    = 4 * lane;         // 4 output cols per lane
    float* outw = out + (size_t)n * (NS * H * W)
                      + (size_t)(y0 + ybase) * W + xo;

    #pragma unroll 1
    for (int s = 0; s < NS; ++s) {
        const int sy = s_sh[2 * s + 0];
        const int sx = s_sh[2 * s + 1];

        // splatted filter pairs (both halves equal) - 25 pairs in registers
        u64 fp[25];
        #pragma unroll
        for (int t = 0; t < 25; ++t) {
            float f = s_f[s * 25 + t];
            fp[t] = pk(f, f);
        }

        const int rowbase = ybase + 4 - sy;     // [0, 16]
        const int col0    = xo + 4 - sx;        // window start

        // w[t] = x_padded[col0 + t], t in [0,8). Aligned base:
        //   sx even -> col0 even -> s_a[col0]
        //   sx odd  -> col0 odd  -> s_b[col0-1]   (s_b[i] = x[i+1])
        const float* base = (sx & 1) ? &s_b[rowbase][col0 - 1]
                                     : &s_a[rowbase][col0];

        u64 acc0[4], acc1[4];   // (xo,xo+1) and (xo+2,xo+3) per row
        #pragma unroll
        for (int y = 0; y < 4; ++y) { acc0[y] = 0ull; acc1[y] = 0ull; }

        #pragma unroll
        for (int k = 0; k < 8; ++k) {
            const float2* r2 = (const float2*)(base + k * SCOLS);
            float2 q0 = r2[0], q1 = r2[1], q2 = r2[2], q3 = r2[3];
            // even-start pairs: alias v2-load pairs (0 MOV)
            u64 e0 = pk(q0.x, q0.y);
            u64 e1 = pk(q1.x, q1.y);
            u64 e2 = pk(q2.x, q2.y);
            u64 e3 = pk(q3.x, q3.y);
            // odd-start (cross) pairs: 2 MOV each
            u64 o0 = pk(q0.y, q1.x);
            u64 o1 = pk(q1.y, q2.x);
            u64 o2 = pk(q2.y, q3.x);

            #pragma unroll
            for (int y = 0; y < 4; ++y) {
                const int i = k - y;          // compile-time after unroll
                if (i >= 0 && i < 5) {
                    const u64* fr = &fp[i * 5];
                    // acc0 taps start at w0..w4 ; acc1 taps start at w2..w6
                    fma2(acc0[y], fr[0], e0);
                    fma2(acc0[y], fr[1], o0);
                    fma2(acc0[y], fr[2], e1);
                    fma2(acc0[y], fr[3], o1);
                    fma2(acc0[y], fr[4], e2);

                    fma2(acc1[y], fr[0], e1);
                    fma2(acc1[y], fr[1], o1);
                    fma2(acc1[y], fr[2], e2);
                    fma2(acc1[y], fr[3], o2);
                    fma2(acc1[y], fr[4], e3);
                }
            }
        }

        float* ops = outw + (size_t)s * (H * W);
        #pragma unroll
        for (int y = 0; y < 4; ++y) {
            ulonglong2 v;
            v.x = acc0[y];
            v.y = acc1[y];
            *(ulonglong2*)(ops + y * W) = v;   // STG.128, 16B aligned
        }
    }
}

extern "C" void kernel_launch(void* const* d_in, const int* in_sizes, int n_in,
                              void* d_out, int out_size)
{
    const float* tens    = (const float*)d_in[0];
    const float* filters = (const float*)d_in[1];
    const int*   shifts  = (const int*)d_in[2];
    float*       out     = (float*)d_out;

    dim3 grid(256, H / TY);   // 2048 blocks
    shifted_conv_kernel<<<grid, 128>>>(tens, filters, shifts, out);
}